// round 2
// baseline (speedup 1.0000x reference)
#include <cuda_runtime.h>
#include <cstdint>
#include <cstddef>

#define F 128
#define N_MAX 100000

// Scratch for H = X@W + b  (allocation-free rule: __device__ global array)
__device__ __align__(16) float g_H[(size_t)N_MAX * F];

// ---------------------------------------------------------------------------
// GEMM: H[N,128] = X[N,128] @ W[128,128] + b[128]
// BM=128, BN=128, BK=8, 256 threads, 8x8 thread tile.
// ---------------------------------------------------------------------------
__global__ void __launch_bounds__(256) gemm_bias_kernel(
    const float* __restrict__ X, const float* __restrict__ W,
    const float* __restrict__ bias, int N)
{
    __shared__ __align__(16) float Xs[8][128];   // [k][row]
    __shared__ __align__(16) float Ws[8][128];   // [k][col]

    const int tid  = threadIdx.x;
    const int trow = tid >> 4;        // 0..15
    const int tcol = tid & 15;        // 0..15
    const int row0 = blockIdx.x * 128;

    float acc[8][8];
#pragma unroll
    for (int i = 0; i < 8; i++)
#pragma unroll
        for (int j = 0; j < 8; j++) acc[i][j] = 0.f;

    // loader indices
    const int lrow = tid >> 1;          // 0..127
    const int lk   = (tid & 1) * 4;     // 0 or 4
    const int wk   = tid >> 5;          // 0..7
    const int wn   = (tid & 31) * 4;    // 0..124

    for (int k0 = 0; k0 < F; k0 += 8) {
        // W tile (coalesced)
        float4 w4 = *(const float4*)(W + (size_t)(k0 + wk) * F + wn);
        *(float4*)&Ws[wk][wn] = w4;
        // X tile (transposed into k-major smem)
        int grow = row0 + lrow;
        float4 x4 = make_float4(0.f, 0.f, 0.f, 0.f);
        if (grow < N) x4 = *(const float4*)(X + (size_t)grow * F + k0 + lk);
        Xs[lk + 0][lrow] = x4.x;
        Xs[lk + 1][lrow] = x4.y;
        Xs[lk + 2][lrow] = x4.z;
        Xs[lk + 3][lrow] = x4.w;
        __syncthreads();

#pragma unroll
        for (int kk = 0; kk < 8; kk++) {
            float4 a0 = *(const float4*)&Xs[kk][trow * 8];
            float4 a1 = *(const float4*)&Xs[kk][trow * 8 + 4];
            float4 b0 = *(const float4*)&Ws[kk][tcol * 8];
            float4 b1 = *(const float4*)&Ws[kk][tcol * 8 + 4];
            float a[8] = {a0.x, a0.y, a0.z, a0.w, a1.x, a1.y, a1.z, a1.w};
            float b[8] = {b0.x, b0.y, b0.z, b0.w, b1.x, b1.y, b1.z, b1.w};
#pragma unroll
            for (int i = 0; i < 8; i++)
#pragma unroll
                for (int j = 0; j < 8; j++)
                    acc[i][j] = fmaf(a[i], b[j], acc[i][j]);
        }
        __syncthreads();
    }

    float bv[8];
#pragma unroll
    for (int j = 0; j < 8; j++) bv[j] = bias[tcol * 8 + j];

#pragma unroll
    for (int i = 0; i < 8; i++) {
        int grow = row0 + trow * 8 + i;
        if (grow < N) {
            float4 o0, o1;
            o0.x = acc[i][0] + bv[0];
            o0.y = acc[i][1] + bv[1];
            o0.z = acc[i][2] + bv[2];
            o0.w = acc[i][3] + bv[3];
            o1.x = acc[i][4] + bv[4];
            o1.y = acc[i][5] + bv[5];
            o1.z = acc[i][6] + bv[6];
            o1.w = acc[i][7] + bv[7];
            *(float4*)(g_H + (size_t)grow * F + tcol * 8)     = o0;
            *(float4*)(g_H + (size_t)grow * F + tcol * 8 + 4) = o1;
        }
    }
}

// ---------------------------------------------------------------------------
// Edge scatter: out[rows[e],:] += H[cols[e],:] * vals[e]
// One warp per edge; each lane handles a float4; vectorized red.global.add.v4
// ---------------------------------------------------------------------------
__global__ void __launch_bounds__(256) scatter_kernel(
    const int* __restrict__ rows, const int* __restrict__ cols,
    const float* __restrict__ vals, float* __restrict__ out, int E)
{
    int gw   = (int)((blockIdx.x * blockDim.x + threadIdx.x) >> 5);
    int lane = threadIdx.x & 31;
    if (gw >= E) return;

    int   r = __ldg(rows + gw);
    int   c = __ldg(cols + gw);
    float v = __ldg(vals + gw);

    const float4* src = (const float4*)(g_H + (size_t)c * F);
    float4 m = __ldg(src + lane);
    m.x *= v; m.y *= v; m.z *= v; m.w *= v;

    float* dst = out + (size_t)r * F + lane * 4;
    asm volatile("red.global.add.v4.f32 [%0], {%1,%2,%3,%4};"
                 :: "l"(dst), "f"(m.x), "f"(m.y), "f"(m.z), "f"(m.w)
                 : "memory");
}

// ---------------------------------------------------------------------------
// ReLU + dropout, reproducing jax.random.bernoulli(jax.random.key(42), 0.9, shape)
// under jax_threefry_partitionable=True (modern JAX default):
//   per element j: counts = iota(uint64) -> x0 = hi32(j) = 0, x1 = lo32(j) = j
//   (bits1, bits2) = threefry2x32(key=(0,42), (x0, x1))
//   bits = bits1 ^ bits2                    (32-bit output path)
//   u = bitcast((bits>>9)|0x3f800000) - 1.0
//   keep = u < 0.9f ; out = keep ? relu(x)/0.9 : 0
// ---------------------------------------------------------------------------
__global__ void __launch_bounds__(256) relu_dropout_kernel(
    float* __restrict__ out, unsigned total)
{
    unsigned j = blockIdx.x * blockDim.x + threadIdx.x;
    if (j >= total) return;

    const unsigned ks0 = 0u;
    const unsigned ks1 = 42u;
    const unsigned ks2 = 0x1BD11BDAu ^ ks0 ^ ks1;   // 0x1BD11BF0

    unsigned x0 = 0u + ks0;       // hi32 of 64-bit counter is 0 (size < 2^32)
    unsigned x1 = j + ks1;

#define TF_R(d) { x0 += x1; x1 = __funnelshift_l(x1, x1, (d)); x1 ^= x0; }
    TF_R(13) TF_R(15) TF_R(26) TF_R(6)
    x0 += ks1; x1 += ks2 + 1u;
    TF_R(17) TF_R(29) TF_R(16) TF_R(24)
    x0 += ks2; x1 += ks0 + 2u;
    TF_R(13) TF_R(15) TF_R(26) TF_R(6)
    x0 += ks0; x1 += ks1 + 3u;
    TF_R(17) TF_R(29) TF_R(16) TF_R(24)
    x0 += ks1; x1 += ks2 + 4u;
    TF_R(13) TF_R(15) TF_R(26) TF_R(6)
    x0 += ks2; x1 += ks0 + 5u;
#undef TF_R

    unsigned bits = x0 ^ x1;
    float u = __uint_as_float((bits >> 9) | 0x3f800000u) - 1.0f;
    float h = fmaxf(out[j], 0.f);
    out[j] = (u < 0.9f) ? h * (1.0f / 0.9f) : 0.0f;
}

// ---------------------------------------------------------------------------
extern "C" void kernel_launch(void* const* d_in, const int* in_sizes, int n_in,
                              void* d_out, int out_size)
{
    const float* X    = (const float*)d_in[0];
    const float* W    = (const float*)d_in[1];
    const float* bias = (const float*)d_in[2];
    const int*   rows = (const int*)d_in[3];
    const int*   cols = (const int*)d_in[4];
    const float* vals = (const float*)d_in[5];
    float* out = (float*)d_out;

    const int N = in_sizes[0] / F;      // 100000
    const int E = in_sizes[3];          // 1600000

    // zero the (0xAA-poisoned) output accumulator
    cudaMemsetAsync(d_out, 0, (size_t)out_size * sizeof(float), 0);

    // H = X @ W + b
    {
        int grid = (N + 127) / 128;
        gemm_bias_kernel<<<grid, 256>>>(X, W, bias, N);
    }

    // scatter-add over edges
    {
        long long threads = (long long)E * 32;
        int grid = (int)((threads + 255) / 256);
        scatter_kernel<<<grid, 256>>>(rows, cols, vals, out, E);
    }

    // relu + exact-JAX dropout (partitionable threefry)
    {
        unsigned total = (unsigned)((size_t)N * F);
        int grid = (int)((total + 255) / 256);
        relu_dropout_kernel<<<grid, 256>>>(out, total);
    }
}

// round 4
// speedup vs baseline: 1.6204x; 1.6204x over previous
#include <cuda_runtime.h>
#include <cstdint>
#include <cstddef>

#define F 128
#define N_MAX 100000
#define E_MAX 1600000
#define NB_MAX 128   // ceil(N_MAX/1024) = 98

// ------------------------- static scratch (no allocs) ----------------------
__device__ __align__(16) float g_H[(size_t)N_MAX * F];          // X@W+b
__device__ unsigned long long g_edge[E_MAX];                    // packed (val<<32 | col), CSR-ordered
__device__ int g_count[N_MAX];                                  // per-row degree (histogram)
__device__ int g_offset[N_MAX + 1];                             // CSR row offsets
__device__ int g_woff[N_MAX];                                   // write cursors for placement
__device__ int g_part[NB_MAX];                                  // scan block partials

// ---------------------------------------------------------------------------
// zero g_count (avoid any non-launch API inside graph capture)
// ---------------------------------------------------------------------------
__global__ void __launch_bounds__(256) zero_count_kernel(int N)
{
    int i = blockIdx.x * blockDim.x + threadIdx.x;
    if (i < N) g_count[i] = 0;
}

// ---------------------------------------------------------------------------
// GEMM: H[N,128] = X[N,128] @ W[128,128] + b[128]
// ---------------------------------------------------------------------------
__global__ void __launch_bounds__(256) gemm_bias_kernel(
    const float* __restrict__ X, const float* __restrict__ W,
    const float* __restrict__ bias, int N)
{
    __shared__ __align__(16) float Xs[8][128];
    __shared__ __align__(16) float Ws[8][128];

    const int tid  = threadIdx.x;
    const int trow = tid >> 4;
    const int tcol = tid & 15;
    const int row0 = blockIdx.x * 128;

    float acc[8][8];
#pragma unroll
    for (int i = 0; i < 8; i++)
#pragma unroll
        for (int j = 0; j < 8; j++) acc[i][j] = 0.f;

    const int lrow = tid >> 1;
    const int lk   = (tid & 1) * 4;
    const int wk   = tid >> 5;
    const int wn   = (tid & 31) * 4;

    for (int k0 = 0; k0 < F; k0 += 8) {
        float4 w4 = *(const float4*)(W + (size_t)(k0 + wk) * F + wn);
        *(float4*)&Ws[wk][wn] = w4;
        int grow = row0 + lrow;
        float4 x4 = make_float4(0.f, 0.f, 0.f, 0.f);
        if (grow < N) x4 = *(const float4*)(X + (size_t)grow * F + k0 + lk);
        Xs[lk + 0][lrow] = x4.x;
        Xs[lk + 1][lrow] = x4.y;
        Xs[lk + 2][lrow] = x4.z;
        Xs[lk + 3][lrow] = x4.w;
        __syncthreads();

#pragma unroll
        for (int kk = 0; kk < 8; kk++) {
            float4 a0 = *(const float4*)&Xs[kk][trow * 8];
            float4 a1 = *(const float4*)&Xs[kk][trow * 8 + 4];
            float4 b0 = *(const float4*)&Ws[kk][tcol * 8];
            float4 b1 = *(const float4*)&Ws[kk][tcol * 8 + 4];
            float a[8] = {a0.x, a0.y, a0.z, a0.w, a1.x, a1.y, a1.z, a1.w};
            float b[8] = {b0.x, b0.y, b0.z, b0.w, b1.x, b1.y, b1.z, b1.w};
#pragma unroll
            for (int i = 0; i < 8; i++)
#pragma unroll
                for (int j = 0; j < 8; j++)
                    acc[i][j] = fmaf(a[i], b[j], acc[i][j]);
        }
        __syncthreads();
    }

    float bv[8];
#pragma unroll
    for (int j = 0; j < 8; j++) bv[j] = bias[tcol * 8 + j];

#pragma unroll
    for (int i = 0; i < 8; i++) {
        int grow = row0 + trow * 8 + i;
        if (grow < N) {
            float4 o0, o1;
            o0.x = acc[i][0] + bv[0]; o0.y = acc[i][1] + bv[1];
            o0.z = acc[i][2] + bv[2]; o0.w = acc[i][3] + bv[3];
            o1.x = acc[i][4] + bv[4]; o1.y = acc[i][5] + bv[5];
            o1.z = acc[i][6] + bv[6]; o1.w = acc[i][7] + bv[7];
            *(float4*)(g_H + (size_t)grow * F + tcol * 8)     = o0;
            *(float4*)(g_H + (size_t)grow * F + tcol * 8 + 4) = o1;
        }
    }
}

// ---------------------------------------------------------------------------
// CSR build
// ---------------------------------------------------------------------------
__global__ void hist_kernel(const int* __restrict__ rows, int E)
{
    int e = blockIdx.x * blockDim.x + threadIdx.x;
    if (e < E) atomicAdd(&g_count[__ldg(rows + e)], 1);
}

// per-1024-block exclusive scan; block total -> g_part[b]
__global__ void __launch_bounds__(1024) scan_partial_kernel(int N)
{
    int i = blockIdx.x * 1024 + threadIdx.x;
    int v = (i < N) ? g_count[i] : 0;
    int lane = threadIdx.x & 31, wid = threadIdx.x >> 5;

    int x = v;
#pragma unroll
    for (int d = 1; d < 32; d <<= 1) {
        int y = __shfl_up_sync(0xffffffffu, x, d);
        if (lane >= d) x += y;
    }
    __shared__ int wsum[32];
    if (lane == 31) wsum[wid] = x;
    __syncthreads();
    if (wid == 0) {
        int w = wsum[lane];
#pragma unroll
        for (int d = 1; d < 32; d <<= 1) {
            int y = __shfl_up_sync(0xffffffffu, w, d);
            if (lane >= d) w += y;
        }
        wsum[lane] = w;
    }
    __syncthreads();
    int base = wid ? wsum[wid - 1] : 0;
    int incl = base + x;
    if (i < N) g_offset[i] = incl - v;           // block-local exclusive
    if (threadIdx.x == 1023) g_part[blockIdx.x] = incl;
}

// exclusive scan of block partials (NB <= 128), single block of 128
__global__ void __launch_bounds__(128) scan_tops_kernel(int NB)
{
    __shared__ int s[128];
    int t = threadIdx.x;
    s[t] = (t < NB) ? g_part[t] : 0;
    __syncthreads();
#pragma unroll
    for (int d = 1; d < 128; d <<= 1) {
        int y = (t >= d) ? s[t - d] : 0;
        __syncthreads();
        s[t] += y;
        __syncthreads();
    }
    if (t < NB) g_part[t] = t ? s[t - 1] : 0;    // exclusive
}

__global__ void __launch_bounds__(1024) scan_add_kernel(int N, int E)
{
    int i = blockIdx.x * 1024 + threadIdx.x;
    if (i < N) {
        int o = g_offset[i] + g_part[i >> 10];
        g_offset[i] = o;
        g_woff[i]   = o;
    }
    if (i == 0) g_offset[N] = E;
}

__global__ void place_kernel(const int* __restrict__ rows,
                             const int* __restrict__ cols,
                             const float* __restrict__ vals, int E)
{
    int e = blockIdx.x * blockDim.x + threadIdx.x;
    if (e >= E) return;
    int r = __ldg(rows + e);
    int p = atomicAdd(&g_woff[r], 1);
    unsigned long long packed =
        ((unsigned long long)__float_as_uint(__ldg(vals + e)) << 32) |
        (unsigned)__ldg(cols + e);
    g_edge[p] = packed;
}

// ---------------------------------------------------------------------------
// threefry2x32-partitionable bits for 32-bit element index j (key = (0,42))
// ---------------------------------------------------------------------------
__device__ __forceinline__ unsigned tf_bits(unsigned j)
{
    const unsigned ks0 = 0u, ks1 = 42u;
    const unsigned ks2 = 0x1BD11BDAu ^ ks0 ^ ks1;
    unsigned x0 = ks0;          // hi32(counter) = 0
    unsigned x1 = j + ks1;
#define TF_R(d) { x0 += x1; x1 = __funnelshift_l(x1, x1, (d)); x1 ^= x0; }
    TF_R(13) TF_R(15) TF_R(26) TF_R(6)
    x0 += ks1; x1 += ks2 + 1u;
    TF_R(17) TF_R(29) TF_R(16) TF_R(24)
    x0 += ks2; x1 += ks0 + 2u;
    TF_R(13) TF_R(15) TF_R(26) TF_R(6)
    x0 += ks0; x1 += ks1 + 3u;
    TF_R(17) TF_R(29) TF_R(16) TF_R(24)
    x0 += ks1; x1 += ks2 + 4u;
    TF_R(13) TF_R(15) TF_R(26) TF_R(6)
    x0 += ks2; x1 += ks0 + 5u;
#undef TF_R
    return x0 ^ x1;
}

__device__ __forceinline__ float drop_apply(float h, unsigned j)
{
    float u = __uint_as_float((tf_bits(j) >> 9) | 0x3f800000u) - 1.0f;
    return (u < 0.9f) ? h * (1.0f / 0.9f) : 0.0f;
}

// ---------------------------------------------------------------------------
// Gather + ReLU + dropout: warp per row.
// out[r,:] = dropout(relu(sum_e H[col_e,:]*val_e))
// ---------------------------------------------------------------------------
__global__ void __launch_bounds__(256) gather_kernel(float* __restrict__ out, int N)
{
    int warp = (blockIdx.x * blockDim.x + threadIdx.x) >> 5;
    int lane = threadIdx.x & 31;
    if (warp >= N) return;
    const int row   = warp;
    const int start = g_offset[row];
    const int end   = g_offset[row + 1];

    float4 acc = make_float4(0.f, 0.f, 0.f, 0.f);

    for (int b = start; b < end; b += 32) {
        int e = b + lane;
        unsigned long long ev = (e < end) ? g_edge[e] : 0ull;
        int cnt = min(32, end - b);
        int i = 0;
        for (; i + 1 < cnt; i += 2) {
            unsigned long long e0 = __shfl_sync(0xffffffffu, ev, i);
            unsigned long long e1 = __shfl_sync(0xffffffffu, ev, i + 1);
            int   c0 = (int)(unsigned)e0;
            int   c1 = (int)(unsigned)e1;
            float v0 = __uint_as_float((unsigned)(e0 >> 32));
            float v1 = __uint_as_float((unsigned)(e1 >> 32));
            float4 m0 = *(const float4*)(g_H + (size_t)c0 * F + lane * 4);
            float4 m1 = *(const float4*)(g_H + (size_t)c1 * F + lane * 4);
            acc.x = fmaf(m0.x, v0, acc.x); acc.y = fmaf(m0.y, v0, acc.y);
            acc.z = fmaf(m0.z, v0, acc.z); acc.w = fmaf(m0.w, v0, acc.w);
            acc.x = fmaf(m1.x, v1, acc.x); acc.y = fmaf(m1.y, v1, acc.y);
            acc.z = fmaf(m1.z, v1, acc.z); acc.w = fmaf(m1.w, v1, acc.w);
        }
        if (i < cnt) {
            unsigned long long e0 = __shfl_sync(0xffffffffu, ev, i);
            int   c0 = (int)(unsigned)e0;
            float v0 = __uint_as_float((unsigned)(e0 >> 32));
            float4 m0 = *(const float4*)(g_H + (size_t)c0 * F + lane * 4);
            acc.x = fmaf(m0.x, v0, acc.x); acc.y = fmaf(m0.y, v0, acc.y);
            acc.z = fmaf(m0.z, v0, acc.z); acc.w = fmaf(m0.w, v0, acc.w);
        }
    }

    // relu
    acc.x = fmaxf(acc.x, 0.f); acc.y = fmaxf(acc.y, 0.f);
    acc.z = fmaxf(acc.z, 0.f); acc.w = fmaxf(acc.w, 0.f);

    // dropout (exact JAX partitionable threefry)
    unsigned j0 = (unsigned)row * F + lane * 4;
    acc.x = drop_apply(acc.x, j0 + 0);
    acc.y = drop_apply(acc.y, j0 + 1);
    acc.z = drop_apply(acc.z, j0 + 2);
    acc.w = drop_apply(acc.w, j0 + 3);

    *(float4*)(out + (size_t)row * F + lane * 4) = acc;
}

// ---------------------------------------------------------------------------
extern "C" void kernel_launch(void* const* d_in, const int* in_sizes, int n_in,
                              void* d_out, int out_size)
{
    const float* X    = (const float*)d_in[0];
    const float* W    = (const float*)d_in[1];
    const float* bias = (const float*)d_in[2];
    const int*   rows = (const int*)d_in[3];
    const int*   cols = (const int*)d_in[4];
    const float* vals = (const float*)d_in[5];
    float* out = (float*)d_out;

    const int N = in_sizes[0] / F;      // 100000
    const int E = in_sizes[3];          // 1600000
    const int NB = (N + 1023) / 1024;   // 98

    // zero degree histogram (kernel, not memset: keep capture launches-only)
    zero_count_kernel<<<(N + 255) / 256, 256>>>(N);

    // H = X @ W + b
    gemm_bias_kernel<<<(N + 127) / 128, 256>>>(X, W, bias, N);

    // CSR build
    hist_kernel<<<(E + 255) / 256, 256>>>(rows, E);
    scan_partial_kernel<<<NB, 1024>>>(N);
    scan_tops_kernel<<<1, 128>>>(NB);
    scan_add_kernel<<<NB, 1024>>>(N, E);
    place_kernel<<<(E + 255) / 256, 256>>>(rows, cols, vals, E);

    // fused gather + relu + dropout (writes every output element)
    {
        int warps_needed = N;
        int grid = (warps_needed * 32 + 255) / 256;
        gather_kernel<<<grid, 256>>>(out, N);
    }
}

// round 5
// speedup vs baseline: 1.6860x; 1.0405x over previous
#include <cuda_runtime.h>
#include <cstdint>
#include <cstddef>

#define F 128
#define N_MAX 100000
#define E_MAX 1600000
#define NB_MAX 128   // ceil(N_MAX/1024) = 98

typedef unsigned long long u64;

// ------------------------- static scratch (no allocs) ----------------------
__device__ __align__(16) float g_H[(size_t)N_MAX * F];          // X@W+b
__device__ unsigned long long g_edge[E_MAX];                    // packed (val<<32 | col), CSR-ordered
__device__ int g_count[N_MAX];                                  // per-row degree (histogram)
__device__ int g_offset[N_MAX + 1];                             // CSR row offsets
__device__ int g_woff[N_MAX];                                   // write cursors for placement
__device__ int g_part[NB_MAX];                                  // scan block partials

// ------------------------- f32x2 packed FMA helpers ------------------------
__device__ __forceinline__ u64 pack2(float lo, float hi)
{
    u64 r;
    asm("mov.b64 %0, {%1, %2};" : "=l"(r) : "f"(lo), "f"(hi));
    return r;
}
__device__ __forceinline__ void fma2(u64& d, u64 a, u64 b)
{
    asm("fma.rn.f32x2 %0, %1, %2, %0;" : "+l"(d) : "l"(a), "l"(b));
}
__device__ __forceinline__ float2 unpack2(u64 v)
{
    float2 f;
    asm("mov.b64 {%0, %1}, %2;" : "=f"(f.x), "=f"(f.y) : "l"(v));
    return f;
}

// ---------------------------------------------------------------------------
// zero g_count (kernel, not memset: keep capture launches-only)
// ---------------------------------------------------------------------------
__global__ void __launch_bounds__(256) zero_count_kernel(int N)
{
    int i = blockIdx.x * blockDim.x + threadIdx.x;
    if (i < N) g_count[i] = 0;
}

// ---------------------------------------------------------------------------
// Fused: GEMM (blocks [0, gemm_blocks)) + row histogram (tail blocks).
// GEMM: H[N,128] = X[N,128] @ W[128,128] + b[128]
//   BM=128, BN=128, BK=8, 256 threads, 8x8 thread tile, packed f32x2 FMA.
// Hist blocks backfill SMs as GEMM waves drain (atomic-bound vs fma-bound).
// ---------------------------------------------------------------------------
__global__ void __launch_bounds__(256) gemm_hist_kernel(
    const float* __restrict__ X, const float* __restrict__ W,
    const float* __restrict__ bias, const int* __restrict__ rows,
    int N, int E, int gemm_blocks)
{
    if ((int)blockIdx.x >= gemm_blocks) {
        // ---- histogram part ----
        int e = ((int)blockIdx.x - gemm_blocks) * 256 + threadIdx.x;
        if (e < E) atomicAdd(&g_count[__ldg(rows + e)], 1);
        return;
    }

    // ---- GEMM part ----
    __shared__ __align__(16) float Xs[8][128];
    __shared__ __align__(16) float Ws[8][128];

    const int tid  = threadIdx.x;
    const int trow = tid >> 4;
    const int tcol = tid & 15;
    const int row0 = blockIdx.x * 128;

    u64 acc2[8][4];
#pragma unroll
    for (int i = 0; i < 8; i++)
#pragma unroll
        for (int j = 0; j < 4; j++) acc2[i][j] = 0ull;

    const int lrow = tid >> 1;
    const int lk   = (tid & 1) * 4;
    const int wk   = tid >> 5;
    const int wn   = (tid & 31) * 4;

    for (int k0 = 0; k0 < F; k0 += 8) {
        float4 w4 = *(const float4*)(W + (size_t)(k0 + wk) * F + wn);
        *(float4*)&Ws[wk][wn] = w4;
        int grow = row0 + lrow;
        float4 x4 = make_float4(0.f, 0.f, 0.f, 0.f);
        if (grow < N) x4 = *(const float4*)(X + (size_t)grow * F + k0 + lk);
        Xs[lk + 0][lrow] = x4.x;
        Xs[lk + 1][lrow] = x4.y;
        Xs[lk + 2][lrow] = x4.z;
        Xs[lk + 3][lrow] = x4.w;
        __syncthreads();

#pragma unroll
        for (int kk = 0; kk < 8; kk++) {
            float4 a0 = *(const float4*)&Xs[kk][trow * 8];
            float4 a1 = *(const float4*)&Xs[kk][trow * 8 + 4];
            float4 b0 = *(const float4*)&Ws[kk][tcol * 8];
            float4 b1 = *(const float4*)&Ws[kk][tcol * 8 + 4];
            u64 bp[4] = { pack2(b0.x, b0.y), pack2(b0.z, b0.w),
                          pack2(b1.x, b1.y), pack2(b1.z, b1.w) };
            float a[8] = {a0.x, a0.y, a0.z, a0.w, a1.x, a1.y, a1.z, a1.w};
#pragma unroll
            for (int i = 0; i < 8; i++) {
                u64 ap = pack2(a[i], a[i]);
#pragma unroll
                for (int j = 0; j < 4; j++)
                    fma2(acc2[i][j], ap, bp[j]);
            }
        }
        __syncthreads();
    }

    float bv[8];
#pragma unroll
    for (int j = 0; j < 8; j++) bv[j] = bias[tcol * 8 + j];

#pragma unroll
    for (int i = 0; i < 8; i++) {
        int grow = row0 + trow * 8 + i;
        if (grow < N) {
            float2 p0 = unpack2(acc2[i][0]);
            float2 p1 = unpack2(acc2[i][1]);
            float2 p2 = unpack2(acc2[i][2]);
            float2 p3 = unpack2(acc2[i][3]);
            float4 o0, o1;
            o0.x = p0.x + bv[0]; o0.y = p0.y + bv[1];
            o0.z = p1.x + bv[2]; o0.w = p1.y + bv[3];
            o1.x = p2.x + bv[4]; o1.y = p2.y + bv[5];
            o1.z = p3.x + bv[6]; o1.w = p3.y + bv[7];
            *(float4*)(g_H + (size_t)grow * F + tcol * 8)     = o0;
            *(float4*)(g_H + (size_t)grow * F + tcol * 8 + 4) = o1;
        }
    }
}

// ---------------------------------------------------------------------------
// CSR build: scans + placement
// ---------------------------------------------------------------------------
__global__ void __launch_bounds__(1024) scan_partial_kernel(int N)
{
    int i = blockIdx.x * 1024 + threadIdx.x;
    int v = (i < N) ? g_count[i] : 0;
    int lane = threadIdx.x & 31, wid = threadIdx.x >> 5;

    int x = v;
#pragma unroll
    for (int d = 1; d < 32; d <<= 1) {
        int y = __shfl_up_sync(0xffffffffu, x, d);
        if (lane >= d) x += y;
    }
    __shared__ int wsum[32];
    if (lane == 31) wsum[wid] = x;
    __syncthreads();
    if (wid == 0) {
        int w = wsum[lane];
#pragma unroll
        for (int d = 1; d < 32; d <<= 1) {
            int y = __shfl_up_sync(0xffffffffu, w, d);
            if (lane >= d) w += y;
        }
        wsum[lane] = w;
    }
    __syncthreads();
    int base = wid ? wsum[wid - 1] : 0;
    int incl = base + x;
    if (i < N) g_offset[i] = incl - v;           // block-local exclusive
    if (threadIdx.x == 1023) g_part[blockIdx.x] = incl;
}

__global__ void __launch_bounds__(128) scan_tops_kernel(int NB)
{
    __shared__ int s[128];
    int t = threadIdx.x;
    s[t] = (t < NB) ? g_part[t] : 0;
    __syncthreads();
#pragma unroll
    for (int d = 1; d < 128; d <<= 1) {
        int y = (t >= d) ? s[t - d] : 0;
        __syncthreads();
        s[t] += y;
        __syncthreads();
    }
    if (t < NB) g_part[t] = t ? s[t - 1] : 0;    // exclusive
}

__global__ void __launch_bounds__(1024) scan_add_kernel(int N, int E)
{
    int i = blockIdx.x * 1024 + threadIdx.x;
    if (i < N) {
        int o = g_offset[i] + g_part[i >> 10];
        g_offset[i] = o;
        g_woff[i]   = o;
    }
    if (i == 0) g_offset[N] = E;
}

__global__ void place_kernel(const int* __restrict__ rows,
                             const int* __restrict__ cols,
                             const float* __restrict__ vals, int E)
{
    int e = blockIdx.x * blockDim.x + threadIdx.x;
    if (e >= E) return;
    int r = __ldg(rows + e);
    int p = atomicAdd(&g_woff[r], 1);
    unsigned long long packed =
        ((unsigned long long)__float_as_uint(__ldg(vals + e)) << 32) |
        (unsigned)__ldg(cols + e);
    g_edge[p] = packed;
}

// ---------------------------------------------------------------------------
// threefry2x32-partitionable bits for element index j (key = (0,42))
// ---------------------------------------------------------------------------
__device__ __forceinline__ unsigned tf_bits(unsigned j)
{
    const unsigned ks0 = 0u, ks1 = 42u;
    const unsigned ks2 = 0x1BD11BDAu ^ ks0 ^ ks1;
    unsigned x0 = ks0;          // hi32(counter) = 0
    unsigned x1 = j + ks1;
#define TF_R(d) { x0 += x1; x1 = __funnelshift_l(x1, x1, (d)); x1 ^= x0; }
    TF_R(13) TF_R(15) TF_R(26) TF_R(6)
    x0 += ks1; x1 += ks2 + 1u;
    TF_R(17) TF_R(29) TF_R(16) TF_R(24)
    x0 += ks2; x1 += ks0 + 2u;
    TF_R(13) TF_R(15) TF_R(26) TF_R(6)
    x0 += ks0; x1 += ks1 + 3u;
    TF_R(17) TF_R(29) TF_R(16) TF_R(24)
    x0 += ks1; x1 += ks2 + 4u;
    TF_R(13) TF_R(15) TF_R(26) TF_R(6)
    x0 += ks2; x1 += ks0 + 5u;
#undef TF_R
    return x0 ^ x1;
}

__device__ __forceinline__ float drop_apply(float h, unsigned j)
{
    float u = __uint_as_float((tf_bits(j) >> 9) | 0x3f800000u) - 1.0f;
    return (u < 0.9f) ? h * (1.0f / 0.9f) : 0.0f;
}

// ---------------------------------------------------------------------------
// Gather + ReLU + dropout: warp per row.
// ---------------------------------------------------------------------------
__global__ void __launch_bounds__(256) gather_kernel(float* __restrict__ out, int N)
{
    int warp = (blockIdx.x * blockDim.x + threadIdx.x) >> 5;
    int lane = threadIdx.x & 31;
    if (warp >= N) return;
    const int row   = warp;
    const int start = g_offset[row];
    const int end   = g_offset[row + 1];

    float4 acc = make_float4(0.f, 0.f, 0.f, 0.f);

    for (int b = start; b < end; b += 32) {
        int e = b + lane;
        unsigned long long ev = (e < end) ? g_edge[e] : 0ull;
        int cnt = min(32, end - b);
        int i = 0;
        for (; i + 1 < cnt; i += 2) {
            unsigned long long e0 = __shfl_sync(0xffffffffu, ev, i);
            unsigned long long e1 = __shfl_sync(0xffffffffu, ev, i + 1);
            int   c0 = (int)(unsigned)e0;
            int   c1 = (int)(unsigned)e1;
            float v0 = __uint_as_float((unsigned)(e0 >> 32));
            float v1 = __uint_as_float((unsigned)(e1 >> 32));
            float4 m0 = *(const float4*)(g_H + (size_t)c0 * F + lane * 4);
            float4 m1 = *(const float4*)(g_H + (size_t)c1 * F + lane * 4);
            acc.x = fmaf(m0.x, v0, acc.x); acc.y = fmaf(m0.y, v0, acc.y);
            acc.z = fmaf(m0.z, v0, acc.z); acc.w = fmaf(m0.w, v0, acc.w);
            acc.x = fmaf(m1.x, v1, acc.x); acc.y = fmaf(m1.y, v1, acc.y);
            acc.z = fmaf(m1.z, v1, acc.z); acc.w = fmaf(m1.w, v1, acc.w);
        }
        if (i < cnt) {
            unsigned long long e0 = __shfl_sync(0xffffffffu, ev, i);
            int   c0 = (int)(unsigned)e0;
            float v0 = __uint_as_float((unsigned)(e0 >> 32));
            float4 m0 = *(const float4*)(g_H + (size_t)c0 * F + lane * 4);
            acc.x = fmaf(m0.x, v0, acc.x); acc.y = fmaf(m0.y, v0, acc.y);
            acc.z = fmaf(m0.z, v0, acc.z); acc.w = fmaf(m0.w, v0, acc.w);
        }
    }

    acc.x = fmaxf(acc.x, 0.f); acc.y = fmaxf(acc.y, 0.f);
    acc.z = fmaxf(acc.z, 0.f); acc.w = fmaxf(acc.w, 0.f);

    unsigned j0 = (unsigned)row * F + lane * 4;
    acc.x = drop_apply(acc.x, j0 + 0);
    acc.y = drop_apply(acc.y, j0 + 1);
    acc.z = drop_apply(acc.z, j0 + 2);
    acc.w = drop_apply(acc.w, j0 + 3);

    *(float4*)(out + (size_t)row * F + lane * 4) = acc;
}

// ---------------------------------------------------------------------------
extern "C" void kernel_launch(void* const* d_in, const int* in_sizes, int n_in,
                              void* d_out, int out_size)
{
    const float* X    = (const float*)d_in[0];
    const float* W    = (const float*)d_in[1];
    const float* bias = (const float*)d_in[2];
    const int*   rows = (const int*)d_in[3];
    const int*   cols = (const int*)d_in[4];
    const float* vals = (const float*)d_in[5];
    float* out = (float*)d_out;

    const int N = in_sizes[0] / F;      // 100000
    const int E = in_sizes[3];          // 1600000
    const int NB = (N + 1023) / 1024;   // 98

    // zero degree histogram
    zero_count_kernel<<<(N + 255) / 256, 256>>>(N);

    // fused H = X@W + b  AND  row histogram (tail blocks)
    {
        int gemm_blocks = (N + 127) / 128;
        int hist_blocks = (E + 255) / 256;
        gemm_hist_kernel<<<gemm_blocks + hist_blocks, 256>>>(
            X, W, bias, rows, N, E, gemm_blocks);
    }

    // CSR offsets + placement
    scan_partial_kernel<<<NB, 1024>>>(N);
    scan_tops_kernel<<<1, 128>>>(NB);
    scan_add_kernel<<<NB, 1024>>>(N, E);
    place_kernel<<<(E + 255) / 256, 256>>>(rows, cols, vals, E);

    // fused gather + relu + dropout
    {
        int grid = (N * 32 + 255) / 256;
        gather_kernel<<<grid, 256>>>(out, N);
    }
}